// round 12
// baseline (speedup 1.0000x reference)
#include <cuda_runtime.h>
#include <math.h>
#include <float.h>

#define NB 64
#define NG 32
#define NA 8400
#define NC 80
#define NCH 84
#define TOPK 13
#define CAP 2048
#define THR 1.2e-12f   // conservative: any IoU=0 anchor has align^2 <= 1e-12*(1+eps)

// Scratch (device globals — no allocation allowed; zero-initialized at load)
__device__ float4             g_pbox[NB * NA];      // decoded pred boxes
__device__ float              g_dinv[NB * NA];      // 1/softmax denominator
__device__ unsigned           g_inside[NB * NA];    // bit g: anchor center inside gt g
__device__ unsigned           g_cand[NB * NA];      // bit g: topk(g) && inside
__device__ int                g_cnt[NB * NG];       // bucket counts (k3 re-zeroes)
__device__ unsigned long long g_bucket[(size_t)NB * NG * CAP];
__device__ int                g_count;
__device__ int                g_ticket;

__device__ __forceinline__ unsigned long long pack_key(float v, int ixv) {
    return ((unsigned long long)__float_as_uint(v) << 32) | (unsigned)(NA - ixv);
}

// ---------------------------------------------------------------------------
// Kernel 0: softmax denominators only. Pure streaming: 2 anchors/thread,
// unroll 10 for deep MLP, minimal registers -> high occupancy.
// ---------------------------------------------------------------------------
__global__ void __launch_bounds__(128) k0_softmax(const float* __restrict__ preds)
{
    const int b  = blockIdx.y;
    const int a2 = blockIdx.x * blockDim.x + threadIdx.x;
    if (a2 >= NA / 2) return;
    const int a = a2 * 2;

    const float* __restrict__ pc = preds + (size_t)b * NCH * NA + (size_t)4 * NA + a;
    float s0 = 0.f, s1 = 0.f;
    #pragma unroll 10
    for (int c = 0; c < NC; ++c) {
        const float2 x = *reinterpret_cast<const float2*>(pc + (size_t)c * NA);
        s0 += __expf(x.x);
        s1 += __expf(x.y);
    }
    *reinterpret_cast<float2*>(&g_dinv[(size_t)b * NA + a]) =
        make_float2(__frcp_rn(s0), __frcp_rn(s1));
}

// ---------------------------------------------------------------------------
// Kernel 1b: decode pred boxes, inside bits, and sparse append of
// (align^2,idx) keys for IoU>0 pairs into per-(b,g) buckets.
// ---------------------------------------------------------------------------
__global__ void __launch_bounds__(128) k1_pairs(const float* __restrict__ preds,
                                                const float* __restrict__ gtb,
                                                const int*   __restrict__ gtc,
                                                const float* __restrict__ anc)
{
    __shared__ float sx1[NG], sy1[NG], sx2[NG], sy2[NG], sar[NG];
    __shared__ int   scls[NG];
    const int b   = blockIdx.y;
    const int tid = threadIdx.x;
    if (tid < NG) {
        const float4 gp = *reinterpret_cast<const float4*>(gtb + ((size_t)b * NG + tid) * 4);
        sx1[tid] = gp.x; sy1[tid] = gp.y; sx2[tid] = gp.z; sy2[tid] = gp.w;
        sar[tid] = (gp.z - gp.x) * (gp.w - gp.y) + 1e-7f;   // area_g + IOU_EPS
        scls[tid] = gtc[b * NG + tid];
    }
    if (blockIdx.x == 0 && b == 0 && tid == 0) { g_count = 0; g_ticket = 0; }
    __syncthreads();

    const int a = (blockIdx.x * blockDim.x + tid) * 4;
    if (a >= NA) return;

    const float* pb = preds + (size_t)b * NCH * NA;

    float ax[4], ay[4];
    {
        const float4 a01 = *reinterpret_cast<const float4*>(anc + (size_t)a * 2);
        const float4 a23 = *reinterpret_cast<const float4*>(anc + (size_t)a * 2 + 4);
        ax[0] = a01.x; ay[0] = a01.y; ax[1] = a01.z; ay[1] = a01.w;
        ax[2] = a23.x; ay[2] = a23.y; ax[3] = a23.z; ay[3] = a23.w;
    }
    const float4 dl = *reinterpret_cast<const float4*>(pb + 0 * NA + a);
    const float4 dt = *reinterpret_cast<const float4*>(pb + 1 * NA + a);
    const float4 dr = *reinterpret_cast<const float4*>(pb + 2 * NA + a);
    const float4 db = *reinterpret_cast<const float4*>(pb + 3 * NA + a);
    const float dlv[4] = {dl.x, dl.y, dl.z, dl.w};
    const float dtv[4] = {dt.x, dt.y, dt.z, dt.w};
    const float drv[4] = {dr.x, dr.y, dr.z, dr.w};
    const float dbv[4] = {db.x, db.y, db.z, db.w};

    const size_t ba = (size_t)b * NA + a;
    const float4 dinv4 = *reinterpret_cast<const float4*>(&g_dinv[ba]);
    const float inv[4] = {dinv4.x, dinv4.y, dinv4.z, dinv4.w};

    float px1[4], py1[4], px2[4], py2[4], areap[4];
    #pragma unroll
    for (int i = 0; i < 4; ++i) {
        px1[i] = ax[i] - dlv[i]; py1[i] = ay[i] - dtv[i];
        px2[i] = ax[i] + drv[i]; py2[i] = ay[i] + dbv[i];
        areap[i] = (px2[i] - px1[i]) * (py2[i] - py1[i]);
        g_pbox[ba + i] = make_float4(px1[i], py1[i], px2[i], py2[i]);
    }

    unsigned ins[4] = {0u, 0u, 0u, 0u};

    #pragma unroll 1
    for (int g = 0; g < NG; ++g) {
        const float gx1 = sx1[g], gy1 = sy1[g], gx2 = sx2[g], gy2 = sy2[g];
        const float ag  = sar[g];
        const int bg = b * NG + g;
        #pragma unroll
        for (int i = 0; i < 4; ++i) {
            const float iw = fmaxf(fminf(px2[i], gx2) - fmaxf(px1[i], gx1), 0.f);
            const float ih = fmaxf(fminf(py2[i], gy2) - fmaxf(py1[i], gy1), 0.f);
            if (iw > 0.f && ih > 0.f) {   // IoU>0: sparse append (~1.3% of pairs)
                const float inter = iw * ih;
                const float iou = __fdividef(inter, areap[i] + ag - inter);
                const float lg  = pb[(size_t)(4 + scls[g]) * NA + a + i];
                const float csc = __expf(lg) * inv[i];
                const float al  = fmaxf(iou, 1e-12f) * csc;   // align^2 (monotone)
                const int pos = atomicAdd(&g_cnt[bg], 1);
                if (pos < CAP)
                    g_bucket[(size_t)bg * CAP + pos] = pack_key(al, a + i);
            }
            // inside test: strict compares (== min(d) > 1e-9 at these scales)
            if ((ax[i] > gx1) && (ay[i] > gy1) && (ax[i] < gx2) && (ay[i] < gy2))
                ins[i] |= (1u << g);
        }
    }
    *reinterpret_cast<uint4*>(&g_inside[ba]) = make_uint4(ins[0], ins[1], ins[2], ins[3]);
    *reinterpret_cast<uint4*>(&g_cand[ba])   = make_uint4(0u, 0u, 0u, 0u);  // zero each replay
}

// ---------------------------------------------------------------------------
// warp ballot-insert of one candidate key into a warp-distributed sorted
// top-13 list (lanes 0..12 hold keys desc).
// ---------------------------------------------------------------------------
__device__ __forceinline__ void warp_insert(unsigned long long bk,
                                            unsigned long long& mykey,
                                            unsigned long long& kmin,
                                            int lane)
{
    if (bk > kmin) {
        const unsigned long long up = __shfl_up_sync(0xffffffffu, mykey, 1);
        if (lane < TOPK && bk > mykey)
            mykey = (lane == 0 || bk <= up) ? bk : up;
        kmin = __shfl_sync(0xffffffffu, mykey, TOPK - 1);
    }
}

// warp 0: merge 2x13 keys from smem, produce winner i on lane i (i<13)
__device__ __forceinline__ unsigned long long warp0_merge26(
    const unsigned long long* sk, int lane)
{
    unsigned long long h = (lane < 2 * TOPK) ? sk[lane] : 0ull;
    unsigned long long win = 0ull;
    #pragma unroll
    for (int it = 0; it < TOPK; ++it) {
        unsigned long long m = h;
        #pragma unroll
        for (int off = 16; off; off >>= 1) {
            const unsigned long long o = __shfl_xor_sync(0xffffffffu, m, off);
            if (o > m) m = o;
        }
        if (h == m) h = 0ull;          // pop (keys distinct)
        if (lane == it) win = m;
    }
    return win;
}

// ---------------------------------------------------------------------------
// Kernel 2: per-(b,g) top-13. Fast path: top-13 of the sparse bucket + guard
// (13th value > THR ⇒ provably equals full-row top-13). Fallback: exact
// full-row recompute from pbox/dinv/logits (bit-identical op sequence).
// ---------------------------------------------------------------------------
__global__ void __launch_bounds__(64) k2_topk(const float* __restrict__ preds,
                                              const float* __restrict__ gtb,
                                              const int*   __restrict__ gtc)
{
    __shared__ unsigned long long sk[2 * TOPK];
    __shared__ int sflag;
    const int g = blockIdx.x;
    const int b = blockIdx.y;
    const int tid = threadIdx.x, lane = tid & 31, w = tid >> 5;
    const int bg = b * NG + g;

    const int cnt = g_cnt[bg];
    bool fb = (cnt > CAP) || (cnt < TOPK);

    if (!fb) {
        const unsigned long long* __restrict__ buck = g_bucket + (size_t)bg * CAP;
        unsigned long long mykey = 0ull, kmin = 0ull;
        for (int base = 0; base < cnt; base += 64) {
            const int i = base + tid;
            const unsigned long long k = (i < cnt) ? buck[i] : 0ull;
            unsigned bal = __ballot_sync(0xffffffffu, k > kmin);
            while (bal) {
                const int src = __ffs(bal) - 1;
                bal &= bal - 1;
                const unsigned long long bk = __shfl_sync(0xffffffffu, k, src);
                warp_insert(bk, mykey, kmin, lane);
            }
        }
        if (lane < TOPK) sk[w * TOPK + lane] = mykey;
        __syncthreads();
        unsigned long long win = 0ull;
        if (w == 0) {
            win = warp0_merge26(sk, lane);
            const unsigned long long w13 = __shfl_sync(0xffffffffu, win, TOPK - 1);
            const float v13 = __uint_as_float((unsigned)(w13 >> 32));
            if (lane == 0) sflag = (v13 > THR) ? 0 : 1;
        }
        __syncthreads();
        fb = (sflag != 0);
        if (!fb) {
            if (w == 0 && lane < TOPK) {
                const int ix = NA - (int)(unsigned)(win & 0xffffffffu);
                const size_t bw = (size_t)b * NA + ix;
                if ((g_inside[bw] >> g) & 1u) atomicOr(&g_cand[bw], 1u << g);
            }
            return;
        }
    }

    // ---- exact fallback: full 8400-anchor scan (rare) ----
    const float4 gp = *reinterpret_cast<const float4*>(gtb + ((size_t)bg) * 4);
    const float ag = (gp.z - gp.x) * (gp.w - gp.y) + 1e-7f;
    const int   cls = gtc[bg];
    const float* __restrict__ lgrow = preds + (size_t)b * NCH * NA + (size_t)(4 + cls) * NA;
    const float4* __restrict__ pbox = g_pbox + (size_t)b * NA;
    const float*  __restrict__ dinv = g_dinv + (size_t)b * NA;

    unsigned long long mykey = 0ull, kmin = 0ull;
    float vmin = 0.f;
    const int half = NA / 2;          // 4200 per warp
    const int qb = w * half;
    for (int it = 0; it < (half + 31) / 32; ++it) {
        const int loc = it * 32 + lane;
        float val = -1.f;
        if (loc < half) {
            const int i = qb + loc;
            const float4 p = pbox[i];
            const float iw = fmaxf(fminf(p.z, gp.z) - fmaxf(p.x, gp.x), 0.f);
            const float ih = fmaxf(fminf(p.w, gp.w) - fmaxf(p.y, gp.y), 0.f);
            const float inter = iw * ih;
            const float ap = (p.z - p.x) * (p.w - p.y);
            const float iou = __fdividef(inter, ap + ag - inter);
            const float csc = __expf(lgrow[i]) * dinv[i];
            val = fmaxf(iou, 1e-12f) * csc;
        }
        unsigned bal = __ballot_sync(0xffffffffu, val >= vmin);
        while (bal) {
            const int src = __ffs(bal) - 1;
            bal &= bal - 1;
            const float bv = __shfl_sync(0xffffffffu, val, src);
            const unsigned long long bk = pack_key(bv, qb + it * 32 + src);
            if (bk > kmin) {
                warp_insert(bk, mykey, kmin, lane);
                vmin = __uint_as_float((unsigned)(kmin >> 32));
            }
        }
    }
    if (lane < TOPK) sk[w * TOPK + lane] = mykey;
    __syncthreads();
    if (w == 0) {
        const unsigned long long win = warp0_merge26(sk, lane);
        if (lane < TOPK) {
            const int ix = NA - (int)(unsigned)(win & 0xffffffffu);
            const size_t bw = (size_t)b * NA + ix;
            if ((g_inside[bw] >> g) & 1u) atomicOr(&g_cand[bw], 1u << g);
        }
    }
}

// ---------------------------------------------------------------------------
// Kernel 3: resolve assignment, recompute ts for fg anchors, write outputs,
// zero bucket counters for next replay; last block writes fg sum.
// out layout: tb(B,A,4) | tc(B,A) | ts(B,A) | fg(B,A) | fg_sum(1)  — all f32
// ---------------------------------------------------------------------------
__global__ void __launch_bounds__(256) k3_out(const float* __restrict__ preds,
                                              const float* __restrict__ gtb,
                                              const int*   __restrict__ gtc,
                                              float* __restrict__ out)
{
    __shared__ float sx1[NG], sy1[NG], sx2[NG], sy2[NG], sar[NG];
    __shared__ int   scls[NG];
    const int b   = blockIdx.y;
    const int tid = threadIdx.x;
    if (tid < NG) {
        const float4 gp = *reinterpret_cast<const float4*>(gtb + ((size_t)b * NG + tid) * 4);
        sx1[tid] = gp.x; sy1[tid] = gp.y; sx2[tid] = gp.z; sy2[tid] = gp.w;
        sar[tid] = (gp.z - gp.x) * (gp.w - gp.y) + 1e-7f;
        scls[tid] = gtc[b * NG + tid];
        if (blockIdx.x == 0) g_cnt[b * NG + tid] = 0;   // reset for next replay
    }
    __syncthreads();

    const int a = blockIdx.x * blockDim.x + tid;
    bool fg = false;
    float x1 = 0.f, y1 = 0.f, x2 = 0.f, y2 = 0.f, ts = 0.f, tcf = 0.f;

    if (a < NA) {
        const size_t ba = (size_t)b * NA + a;
        const unsigned m = g_cand[ba];
        const int pc = __popc(m);
        fg = (pc > 0);
        if (fg) {
            const float4 p = g_pbox[ba];
            const float ap = (p.z - p.x) * (p.w - p.y);
            int g;
            if (pc == 1) {
                g = __ffs(m) - 1;
            } else {
                // argmax_g IoU (first max) — rare path
                float bi = -1.f; int bgx = 0;
                #pragma unroll 1
                for (int gg = 0; gg < NG; ++gg) {
                    const float iw = fmaxf(fminf(p.z, sx2[gg]) - fmaxf(p.x, sx1[gg]), 0.f);
                    const float ih = fmaxf(fminf(p.w, sy2[gg]) - fmaxf(p.y, sy1[gg]), 0.f);
                    const float inter = iw * ih;
                    const float iou = __fdividef(inter, ap + sar[gg] - inter);
                    if (iou > bi) { bi = iou; bgx = gg; }
                }
                g = bgx;
            }
            x1 = sx1[g]; y1 = sy1[g]; x2 = sx2[g]; y2 = sy2[g];
            tcf = (float)scls[g];
            // recompute ts = sqrt(align^2) for the chosen gt
            const float iw = fmaxf(fminf(p.z, x2) - fmaxf(p.x, x1), 0.f);
            const float ih = fmaxf(fminf(p.w, y2) - fmaxf(p.y, y1), 0.f);
            const float inter = iw * ih;
            const float iou = __fdividef(inter, ap + sar[g] - inter);
            const float lg = preds[(size_t)b * NCH * NA + (size_t)(4 + scls[g]) * NA + a];
            const float csc = __expf(lg) * g_dinv[ba];
            ts = sqrtf(fmaxf(iou, 1e-12f) * csc);
        }
    }

    const size_t BA = (size_t)NB * NA;
    if (a < NA) {
        const size_t ba = (size_t)b * NA + a;
        *reinterpret_cast<float4*>(out + ba * 4) = make_float4(x1, y1, x2, y2);
        out[BA * 4 + ba] = tcf;
        out[BA * 5 + ba] = ts;
        out[BA * 6 + ba] = fg ? 1.f : 0.f;
    }
    const unsigned bal = __ballot_sync(0xffffffffu, fg);
    if ((tid & 31) == 0 && bal) atomicAdd(&g_count, __popc(bal));

    __syncthreads();
    if (tid == 0) {
        __threadfence();
        const int nblk = gridDim.x * gridDim.y;
        if (atomicAdd(&g_ticket, 1) == nblk - 1) {
            out[BA * 7] = (float)atomicAdd(&g_count, 0);
        }
    }
}

// ---------------------------------------------------------------------------
extern "C" void kernel_launch(void* const* d_in, const int* in_sizes, int n_in,
                              void* d_out, int out_size)
{
    const float* preds = (const float*)d_in[0];
    const float* gtb   = (const float*)d_in[1];
    const int*   gtc   = (const int*)  d_in[2];
    const float* anc   = (const float*)d_in[3];
    float*       out   = (float*)d_out;

    dim3 grid0((NA / 2 + 127) / 128, NB);   // 33 x 64
    k0_softmax<<<grid0, 128>>>(preds);

    dim3 grid1((NA / 4 + 127) / 128, NB);   // 17 x 64
    k1_pairs<<<grid1, 128>>>(preds, gtb, gtc, anc);

    dim3 grid2(NG, NB);                     // 32 x 64
    k2_topk<<<grid2, 64>>>(preds, gtb, gtc);

    dim3 grid3((NA + 255) / 256, NB);       // 33 x 64
    k3_out<<<grid3, 256>>>(preds, gtb, gtc, out);
}

// round 15
// speedup vs baseline: 1.1682x; 1.1682x over previous
#include <cuda_runtime.h>
#include <math.h>
#include <float.h>

#define NB 64
#define NG 32
#define NA 8400
#define NC 80
#define NCH 84
#define TOPK 13
#define CAP 2048
#define THR 1.2e-12f   // conservative: any IoU=0 anchor has align^2 <= 1e-12*(1+eps)

// Scratch (device globals — no allocation allowed; zero-initialized at load)
__device__ float4             g_pbox[NB * NA];      // decoded pred boxes
__device__ float              g_dinv[NB * NA];      // 1/softmax denominator
__device__ unsigned           g_inside[NB * NA];    // bit g: anchor center inside gt g
__device__ unsigned           g_cand[NB * NA];      // bit g: topk(g) && inside
__device__ int                g_cnt[NB * NG];       // bucket counts (k3 re-zeroes)
__device__ unsigned long long g_bucket[(size_t)NB * NG * CAP];
__device__ int                g_count;
__device__ int                g_ticket;

__device__ __forceinline__ unsigned long long pack_key(float v, int ixv) {
    return ((unsigned long long)__float_as_uint(v) << 32) | (unsigned)(NA - ixv);
}

// ---------------------------------------------------------------------------
// Kernel 1: decode pred boxes, softmax denominators, inside bits, and sparse
// append of (align^2,idx) keys for IoU>0 pairs into per-(b,g) buckets.
// Block-bbox gt pruning: a gt that misses the union bbox of all pred boxes in
// the block can yield neither IoU>0 nor inside (anchor centers are strictly
// inside their pred boxes since dist >= 1) -> skip it entirely.
// ---------------------------------------------------------------------------
__global__ void __launch_bounds__(128, 8) k1_align(const float* __restrict__ preds,
                                                   const float* __restrict__ gtb,
                                                   const int*   __restrict__ gtc,
                                                   const float* __restrict__ anc)
{
    __shared__ float sx1[NG], sy1[NG], sx2[NG], sy2[NG], sar[NG];
    __shared__ int   scls[NG];
    __shared__ float swx1[4], swy1[4], swx2[4], swy2[4];
    const int b   = blockIdx.y;
    const int tid = threadIdx.x;
    const int lane = tid & 31, wid = tid >> 5;
    if (tid < NG) {
        const float4 gp = *reinterpret_cast<const float4*>(gtb + ((size_t)b * NG + tid) * 4);
        sx1[tid] = gp.x; sy1[tid] = gp.y; sx2[tid] = gp.z; sy2[tid] = gp.w;
        sar[tid] = (gp.z - gp.x) * (gp.w - gp.y) + 1e-7f;   // area_g + IOU_EPS
        scls[tid] = gtc[b * NG + tid];
    }
    if (blockIdx.x == 0 && b == 0 && tid == 0) { g_count = 0; g_ticket = 0; }

    const int a = (blockIdx.x * blockDim.x + tid) * 4;
    const bool act = (a < NA);

    const float* pb = preds + (size_t)b * NCH * NA;
    float ax[4], ay[4], px1[4], py1[4], px2[4], py2[4], areap[4];
    float inv[4];
    float tx1 = FLT_MAX, ty1 = FLT_MAX, tx2 = -FLT_MAX, ty2 = -FLT_MAX;
    const size_t ba = (size_t)b * NA + a;
    if (act) {
        const float4 a01 = *reinterpret_cast<const float4*>(anc + (size_t)a * 2);
        const float4 a23 = *reinterpret_cast<const float4*>(anc + (size_t)a * 2 + 4);
        ax[0] = a01.x; ay[0] = a01.y; ax[1] = a01.z; ay[1] = a01.w;
        ax[2] = a23.x; ay[2] = a23.y; ax[3] = a23.z; ay[3] = a23.w;
        const float4 dl = *reinterpret_cast<const float4*>(pb + 0 * NA + a);
        const float4 dt = *reinterpret_cast<const float4*>(pb + 1 * NA + a);
        const float4 dr = *reinterpret_cast<const float4*>(pb + 2 * NA + a);
        const float4 db = *reinterpret_cast<const float4*>(pb + 3 * NA + a);
        const float dlv[4] = {dl.x, dl.y, dl.z, dl.w};
        const float dtv[4] = {dt.x, dt.y, dt.z, dt.w};
        const float drv[4] = {dr.x, dr.y, dr.z, dr.w};
        const float dbv[4] = {db.x, db.y, db.z, db.w};
        #pragma unroll
        for (int i = 0; i < 4; ++i) {
            px1[i] = ax[i] - dlv[i]; py1[i] = ay[i] - dtv[i];
            px2[i] = ax[i] + drv[i]; py2[i] = ay[i] + dbv[i];
            areap[i] = (px2[i] - px1[i]) * (py2[i] - py1[i]);
            g_pbox[ba + i] = make_float4(px1[i], py1[i], px2[i], py2[i]);
            tx1 = fminf(tx1, px1[i]); ty1 = fminf(ty1, py1[i]);
            tx2 = fmaxf(tx2, px2[i]); ty2 = fmaxf(ty2, py2[i]);
        }
        // single-pass softmax denominators
        float s0 = 0.f, s1 = 0.f, s2 = 0.f, s3 = 0.f;
        #pragma unroll 4
        for (int c = 0; c < NC; ++c) {
            const float4 x = *reinterpret_cast<const float4*>(pb + (size_t)(4 + c) * NA + a);
            s0 += __expf(x.x); s1 += __expf(x.y); s2 += __expf(x.z); s3 += __expf(x.w);
        }
        inv[0] = __frcp_rn(s0); inv[1] = __frcp_rn(s1);
        inv[2] = __frcp_rn(s2); inv[3] = __frcp_rn(s3);
        *reinterpret_cast<float4*>(&g_dinv[ba]) = make_float4(inv[0], inv[1], inv[2], inv[3]);
    }

    // block bbox of all pred boxes (inactive lanes contribute sentinels)
    #pragma unroll
    for (int off = 16; off; off >>= 1) {
        tx1 = fminf(tx1, __shfl_xor_sync(0xffffffffu, tx1, off));
        ty1 = fminf(ty1, __shfl_xor_sync(0xffffffffu, ty1, off));
        tx2 = fmaxf(tx2, __shfl_xor_sync(0xffffffffu, tx2, off));
        ty2 = fmaxf(ty2, __shfl_xor_sync(0xffffffffu, ty2, off));
    }
    if (lane == 0) { swx1[wid] = tx1; swy1[wid] = ty1; swx2[wid] = tx2; swy2[wid] = ty2; }
    __syncthreads();
    float bbx1 = swx1[0], bby1 = swy1[0], bbx2 = swx2[0], bby2 = swy2[0];
    #pragma unroll
    for (int wdx = 1; wdx < 4; ++wdx) {
        bbx1 = fminf(bbx1, swx1[wdx]); bby1 = fminf(bby1, swy1[wdx]);
        bbx2 = fmaxf(bbx2, swx2[wdx]); bby2 = fmaxf(bby2, swy2[wdx]);
    }

    unsigned ins[4] = {0u, 0u, 0u, 0u};

    #pragma unroll 1
    for (int g = 0; g < NG; ++g) {
        const float gx1 = sx1[g], gy1 = sy1[g], gx2 = sx2[g], gy2 = sy2[g];
        // block-uniform prune: gt cannot touch any pred box in this block
        if (gx1 >= bbx2 || gx2 <= bbx1 || gy1 >= bby2 || gy2 <= bby1) continue;
        float iwv[4], ihv[4];
        int hits = 0;
        if (act) {
            #pragma unroll
            for (int i = 0; i < 4; ++i) {
                iwv[i] = fminf(px2[i], gx2) - fmaxf(px1[i], gx1);
                ihv[i] = fminf(py2[i], gy2) - fmaxf(py1[i], gy1);
                if (iwv[i] > 0.f && ihv[i] > 0.f) hits |= (1 << i);
            }
        }
        if (hits) {
            const int bg = b * NG + g;
            const float ag = sar[g];
            int pos = atomicAdd(&g_cnt[bg], __popc(hits));
            #pragma unroll
            for (int i = 0; i < 4; ++i) {
                if (hits & (1 << i)) {
                    const float inter = iwv[i] * ihv[i];
                    const float iou = __fdividef(inter, areap[i] + ag - inter);
                    const float lg  = pb[(size_t)(4 + scls[g]) * NA + a + i];
                    const float csc = __expf(lg) * inv[i];
                    const float al  = fmaxf(iou, 1e-12f) * csc;   // align^2 (monotone)
                    if (pos < CAP)
                        g_bucket[(size_t)bg * CAP + pos] = pack_key(al, a + i);
                    ++pos;
                    // inside test (inside ⊆ hit): strict compares == min(d)>1e-9
                    if ((ax[i] > gx1) && (ay[i] > gy1) && (ax[i] < gx2) && (ay[i] < gy2))
                        ins[i] |= (1u << g);
                }
            }
        }
    }
    if (act) {
        *reinterpret_cast<uint4*>(&g_inside[ba]) = make_uint4(ins[0], ins[1], ins[2], ins[3]);
        *reinterpret_cast<uint4*>(&g_cand[ba])   = make_uint4(0u, 0u, 0u, 0u);  // zero each replay
    }
}

// ---------------------------------------------------------------------------
// warp ballot-insert of one candidate key into a warp-distributed sorted
// top-13 list (lanes 0..12 hold keys desc).
// ---------------------------------------------------------------------------
__device__ __forceinline__ void warp_insert(unsigned long long bk,
                                            unsigned long long& mykey,
                                            unsigned long long& kmin,
                                            int lane)
{
    if (bk > kmin) {
        const unsigned long long up = __shfl_up_sync(0xffffffffu, mykey, 1);
        if (lane < TOPK && bk > mykey)
            mykey = (lane == 0 || bk <= up) ? bk : up;
        kmin = __shfl_sync(0xffffffffu, mykey, TOPK - 1);
    }
}

// warp 0: merge 2x13 keys from smem, produce winner i on lane i (i<13)
__device__ __forceinline__ unsigned long long warp0_merge26(
    const unsigned long long* sk, int lane)
{
    unsigned long long h = (lane < 2 * TOPK) ? sk[lane] : 0ull;
    unsigned long long win = 0ull;
    #pragma unroll
    for (int it = 0; it < TOPK; ++it) {
        unsigned long long m = h;
        #pragma unroll
        for (int off = 16; off; off >>= 1) {
            const unsigned long long o = __shfl_xor_sync(0xffffffffu, m, off);
            if (o > m) m = o;
        }
        if (h == m) h = 0ull;          // pop (keys distinct)
        if (lane == it) win = m;
    }
    return win;
}

// ---------------------------------------------------------------------------
// Kernel 2: per-(b,g) top-13. Fast path: top-13 of the sparse bucket + guard
// (13th value > THR ⇒ provably equals full-row top-13). Fallback: exact
// full-row recompute from pbox/dinv/logits (bit-identical op sequence).
// ---------------------------------------------------------------------------
__global__ void __launch_bounds__(64) k2_topk(const float* __restrict__ preds,
                                              const float* __restrict__ gtb,
                                              const int*   __restrict__ gtc)
{
    __shared__ unsigned long long sk[2 * TOPK];
    __shared__ int sflag;
    const int g = blockIdx.x;
    const int b = blockIdx.y;
    const int tid = threadIdx.x, lane = tid & 31, w = tid >> 5;
    const int bg = b * NG + g;

    const int cnt = g_cnt[bg];
    bool fb = (cnt > CAP) || (cnt < TOPK);

    if (!fb) {
        const unsigned long long* __restrict__ buck = g_bucket + (size_t)bg * CAP;
        unsigned long long mykey = 0ull, kmin = 0ull;
        for (int base = 0; base < cnt; base += 64) {
            const int i = base + tid;
            const unsigned long long k = (i < cnt) ? buck[i] : 0ull;
            unsigned bal = __ballot_sync(0xffffffffu, k > kmin);
            while (bal) {
                const int src = __ffs(bal) - 1;
                bal &= bal - 1;
                const unsigned long long bk = __shfl_sync(0xffffffffu, k, src);
                warp_insert(bk, mykey, kmin, lane);
            }
        }
        if (lane < TOPK) sk[w * TOPK + lane] = mykey;
        __syncthreads();
        unsigned long long win = 0ull;
        if (w == 0) {
            win = warp0_merge26(sk, lane);
            const unsigned long long w13 = __shfl_sync(0xffffffffu, win, TOPK - 1);
            const float v13 = __uint_as_float((unsigned)(w13 >> 32));
            if (lane == 0) sflag = (v13 > THR) ? 0 : 1;
        }
        __syncthreads();
        fb = (sflag != 0);
        if (!fb) {
            if (w == 0 && lane < TOPK) {
                const int ix = NA - (int)(unsigned)(win & 0xffffffffu);
                const size_t bw = (size_t)b * NA + ix;
                if ((g_inside[bw] >> g) & 1u) atomicOr(&g_cand[bw], 1u << g);
            }
            return;
        }
    }

    // ---- exact fallback: full 8400-anchor scan (rare) ----
    const float4 gp = *reinterpret_cast<const float4*>(gtb + ((size_t)bg) * 4);
    const float ag = (gp.z - gp.x) * (gp.w - gp.y) + 1e-7f;
    const int   cls = gtc[bg];
    const float* __restrict__ lgrow = preds + (size_t)b * NCH * NA + (size_t)(4 + cls) * NA;
    const float4* __restrict__ pbox = g_pbox + (size_t)b * NA;
    const float*  __restrict__ dinv = g_dinv + (size_t)b * NA;

    unsigned long long mykey = 0ull, kmin = 0ull;
    float vmin = 0.f;
    const int half = NA / 2;          // 4200 per warp
    const int qb = w * half;
    for (int it = 0; it < (half + 31) / 32; ++it) {
        const int loc = it * 32 + lane;
        float val = -1.f;
        if (loc < half) {
            const int i = qb + loc;
            const float4 p = pbox[i];
            const float iw = fmaxf(fminf(p.z, gp.z) - fmaxf(p.x, gp.x), 0.f);
            const float ih = fmaxf(fminf(p.w, gp.w) - fmaxf(p.y, gp.y), 0.f);
            const float inter = iw * ih;
            const float ap = (p.z - p.x) * (p.w - p.y);
            const float iou = __fdividef(inter, ap + ag - inter);
            const float csc = __expf(lgrow[i]) * dinv[i];
            val = fmaxf(iou, 1e-12f) * csc;
        }
        unsigned bal = __ballot_sync(0xffffffffu, val >= vmin);
        while (bal) {
            const int src = __ffs(bal) - 1;
            bal &= bal - 1;
            const float bv = __shfl_sync(0xffffffffu, val, src);
            const unsigned long long bk = pack_key(bv, qb + it * 32 + src);
            if (bk > kmin) {
                warp_insert(bk, mykey, kmin, lane);
                vmin = __uint_as_float((unsigned)(kmin >> 32));
            }
        }
    }
    if (lane < TOPK) sk[w * TOPK + lane] = mykey;
    __syncthreads();
    if (w == 0) {
        const unsigned long long win = warp0_merge26(sk, lane);
        if (lane < TOPK) {
            const int ix = NA - (int)(unsigned)(win & 0xffffffffu);
            const size_t bw = (size_t)b * NA + ix;
            if ((g_inside[bw] >> g) & 1u) atomicOr(&g_cand[bw], 1u << g);
        }
    }
}

// ---------------------------------------------------------------------------
// Kernel 3: resolve assignment, recompute ts for fg anchors, write outputs,
// zero bucket counters for next replay; last block writes fg sum.
// out layout: tb(B,A,4) | tc(B,A) | ts(B,A) | fg(B,A) | fg_sum(1)  — all f32
// ---------------------------------------------------------------------------
__global__ void __launch_bounds__(256) k3_out(const float* __restrict__ preds,
                                              const float* __restrict__ gtb,
                                              const int*   __restrict__ gtc,
                                              float* __restrict__ out)
{
    __shared__ float sx1[NG], sy1[NG], sx2[NG], sy2[NG], sar[NG];
    __shared__ int   scls[NG];
    const int b   = blockIdx.y;
    const int tid = threadIdx.x;
    if (tid < NG) {
        const float4 gp = *reinterpret_cast<const float4*>(gtb + ((size_t)b * NG + tid) * 4);
        sx1[tid] = gp.x; sy1[tid] = gp.y; sx2[tid] = gp.z; sy2[tid] = gp.w;
        sar[tid] = (gp.z - gp.x) * (gp.w - gp.y) + 1e-7f;
        scls[tid] = gtc[b * NG + tid];
        if (blockIdx.x == 0) g_cnt[b * NG + tid] = 0;   // reset for next replay
    }
    __syncthreads();

    const int a = blockIdx.x * blockDim.x + tid;
    bool fg = false;
    float x1 = 0.f, y1 = 0.f, x2 = 0.f, y2 = 0.f, ts = 0.f, tcf = 0.f;

    if (a < NA) {
        const size_t ba = (size_t)b * NA + a;
        const unsigned m = g_cand[ba];
        const int pc = __popc(m);
        fg = (pc > 0);
        if (fg) {
            const float4 p = g_pbox[ba];
            const float ap = (p.z - p.x) * (p.w - p.y);
            int g;
            if (pc == 1) {
                g = __ffs(m) - 1;
            } else {
                // argmax_g IoU (first max) — rare path
                float bi = -1.f; int bgx = 0;
                #pragma unroll 1
                for (int gg = 0; gg < NG; ++gg) {
                    const float iw = fmaxf(fminf(p.z, sx2[gg]) - fmaxf(p.x, sx1[gg]), 0.f);
                    const float ih = fmaxf(fminf(p.w, sy2[gg]) - fmaxf(p.y, sy1[gg]), 0.f);
                    const float inter = iw * ih;
                    const float iou = __fdividef(inter, ap + sar[gg] - inter);
                    if (iou > bi) { bi = iou; bgx = gg; }
                }
                g = bgx;
            }
            x1 = sx1[g]; y1 = sy1[g]; x2 = sx2[g]; y2 = sy2[g];
            tcf = (float)scls[g];
            // recompute ts = sqrt(align^2) for the chosen gt
            const float iw = fmaxf(fminf(p.z, x2) - fmaxf(p.x, x1), 0.f);
            const float ih = fmaxf(fminf(p.w, y2) - fmaxf(p.y, y1), 0.f);
            const float inter = iw * ih;
            const float iou = __fdividef(inter, ap + sar[g] - inter);
            const float lg = preds[(size_t)b * NCH * NA + (size_t)(4 + scls[g]) * NA + a];
            const float csc = __expf(lg) * g_dinv[ba];
            ts = sqrtf(fmaxf(iou, 1e-12f) * csc);
        }
    }

    const size_t BA = (size_t)NB * NA;
    if (a < NA) {
        const size_t ba = (size_t)b * NA + a;
        *reinterpret_cast<float4*>(out + ba * 4) = make_float4(x1, y1, x2, y2);
        out[BA * 4 + ba] = tcf;
        out[BA * 5 + ba] = ts;
        out[BA * 6 + ba] = fg ? 1.f : 0.f;
    }
    const unsigned bal = __ballot_sync(0xffffffffu, fg);
    if ((tid & 31) == 0 && bal) atomicAdd(&g_count, __popc(bal));

    __syncthreads();
    if (tid == 0) {
        __threadfence();
        const int nblk = gridDim.x * gridDim.y;
        if (atomicAdd(&g_ticket, 1) == nblk - 1) {
            out[BA * 7] = (float)atomicAdd(&g_count, 0);
        }
    }
}

// ---------------------------------------------------------------------------
// Launch: plain sequential default-stream launches (graph-capture safe,
// identical structure to the passing 97.6us round).
// ---------------------------------------------------------------------------
extern "C" void kernel_launch(void* const* d_in, const int* in_sizes, int n_in,
                              void* d_out, int out_size)
{
    const float* preds = (const float*)d_in[0];
    const float* gtb   = (const float*)d_in[1];
    const int*   gtc   = (const int*)  d_in[2];
    const float* anc   = (const float*)d_in[3];
    float*       out   = (float*)d_out;

    dim3 grid1((NA / 4 + 127) / 128, NB);   // 17 x 64
    k1_align<<<grid1, 128>>>(preds, gtb, gtc, anc);

    dim3 grid2(NG, NB);                     // 32 x 64
    k2_topk<<<grid2, 64>>>(preds, gtb, gtc);

    dim3 grid3((NA + 255) / 256, NB);       // 33 x 64
    k3_out<<<grid3, 256>>>(preds, gtb, gtc, out);
}